// round 16
// baseline (speedup 1.0000x reference)
#include <cuda_runtime.h>
#include <cuda_fp16.h>
#include <cstdint>
#include <math_constants.h>

// Mahalanobis max-score: cp.async 3-stage warp-private pipeline + all-register
// HMMA, 32-row tiles (two independent 16-row m16n8k16 streams per warp, shared Bf).
// Scalar-lean: write-init MMAs (no zero-init movs), hi-only A frags, fold weight
// w = 2f - float(fh) with exact f re-read from the live stage.
//   B cols 0..63: P fp16 (k-perm pi / n-perm sigma -> a-frags are raw float4s)
//   cols 64..73: hi fp16 of muP columns (classes), 74..79 zero pad
// qf = sum_k (2f - fh)[k] * D[m,k]  ( = f P f - e P e, e = f - fh, ~2^-22 )
// out[m] = alpha * (max_c (D_c - 0.5 qmu_c) - 0.5 * qf)

#define DD 64
#define CC 10
#define NT 10

static __device__ __forceinline__ uint32_t smem_u32(const void* p) {
    uint32_t a;
    asm("{ .reg .u64 t; cvta.to.shared.u64 t, %1; cvt.u32.u64 %0, t; }" : "=r"(a) : "l"(p));
    return a;
}
static __device__ __forceinline__ void cp_async16(uint32_t dst, const void* src) {
    asm volatile("cp.async.cg.shared.global [%0], [%1], 16;" :: "r"(dst), "l"(src) : "memory");
}
static __device__ __forceinline__ void cp_commit() {
    asm volatile("cp.async.commit_group;" ::: "memory");
}
static __device__ __forceinline__ void cp_wait1() {
    asm volatile("cp.async.wait_group 1;" ::: "memory");
}
static __device__ __forceinline__ float4 lds128(uint32_t addr) {
    float4 v;
    asm volatile("ld.shared.v4.f32 {%0,%1,%2,%3}, [%4];"
                 : "=f"(v.x), "=f"(v.y), "=f"(v.z), "=f"(v.w) : "r"(addr));
    return v;
}
// accumulate form: d += a*b
static __device__ __forceinline__ void mma16816(float* d, const uint32_t* a, const uint32_t* b) {
    asm volatile(
        "mma.sync.aligned.m16n8k16.row.col.f32.f16.f16.f32 "
        "{%0,%1,%2,%3}, {%4,%5,%6,%7}, {%8,%9}, {%0,%1,%2,%3};"
        : "+f"(d[0]), "+f"(d[1]), "+f"(d[2]), "+f"(d[3])
        : "r"(a[0]), "r"(a[1]), "r"(a[2]), "r"(a[3]), "r"(b[0]), "r"(b[1]));
}
// write-init form: d = a*b + 0 (no accumulator pre-zeroing needed)
static __device__ __forceinline__ void mma16816_z(float* d, const uint32_t* a, const uint32_t* b) {
    asm volatile(
        "mma.sync.aligned.m16n8k16.row.col.f32.f16.f16.f32 "
        "{%0,%1,%2,%3}, {%4,%5,%6,%7}, {%8,%9}, {%10,%10,%10,%10};"
        : "=f"(d[0]), "=f"(d[1]), "=f"(d[2]), "=f"(d[3])
        : "r"(a[0]), "r"(a[1]), "r"(a[2]), "r"(a[3]), "r"(b[0]), "r"(b[1]), "f"(0.f));
}
static __device__ __forceinline__ uint32_t pack_h2(__half a, __half b) {
    union { __half2 h; uint32_t u; } cv; cv.h = __halves2half2(a, b); return cv.u;
}
static __device__ __forceinline__ float2 h2f(uint32_t u) {
    union { uint32_t u; __half2 h; } cv; cv.u = u; return __half22float2(cv.h);
}
static __device__ __forceinline__ uint32_t cvt_h2(float x, float y) {
    union { __half2 h; uint32_t u; } cv;
    cv.h = __float22half2_rn(make_float2(x, y));
    return cv.u;
}
// stage layout: [32 rows][16 chunks of 16B]; chunk' = c ^ ((row & 3) << 2)
static __device__ __forceinline__ uint32_t st_off(int row, int c) {
    return (uint32_t)(row * 256 + ((c ^ ((row & 3) << 2)) << 4));
}

__global__ __launch_bounds__(128, 2)
void mahal_v16(const float* __restrict__ F, const float* __restrict__ mu,
               const float* __restrict__ P, const float* __restrict__ alpha_p,
               float* __restrict__ out, int nTiles32) {
    extern __shared__ __align__(16) uint8_t dynStage[];   // 4 warps x 3 stages x 8KB
    __shared__ float sMuP[CC * DD];
    __shared__ float sNegQ[16];

    const int tid = threadIdx.x;

    // ---- one-time prep: muP (fp32), -0.5*qmu ----
    for (int idx = tid; idx < CC * DD; idx += 128) {
        int c = idx >> 6, k = idx & 63;
        const float* mc = mu + c * DD;
        const float* pk = P + k * DD;        // P symmetric
        float s = 0.f;
        #pragma unroll 16
        for (int j = 0; j < DD; j++) s = fmaf(mc[j], pk[j], s);
        sMuP[idx] = s;
    }
    __syncthreads();
    if (tid < 16) {
        float v = 0.f;
        if (tid < CC) {
            float qq = 0.f;
            #pragma unroll 16
            for (int k = 0; k < DD; k++) qq = fmaf(sMuP[tid * DD + k], mu[tid * DD + k], qq);
            v = -0.5f * qq;
        }
        sNegQ[tid] = v;
    }
    __syncthreads();

    const int w  = tid >> 5;
    const int l  = tid & 31;
    const int q  = l & 3;
    const int tq = l >> 2;
    const uint32_t uStage = smem_u32(dynStage) + (uint32_t)w * 24576u;

    // ---- persistent B fragments, permuted layout (validated R10/R14/R15) ----
    uint32_t Bf[4][NT][2];
    #pragma unroll
    for (int kk = 0; kk < 4; kk++) {
        const int kb = 16 * kk + 4 * q;
        #pragma unroll
        for (int nt = 0; nt < NT; nt++) {
            uint32_t b0, b1;
            if (nt < 8) {
                int pcol = 16 * (nt >> 1) + 4 * (tq >> 1) + 2 * (nt & 1) + (tq & 1);
                b0 = pack_h2(__float2half_rn(P[(kb    ) * DD + pcol]),
                             __float2half_rn(P[(kb + 1) * DD + pcol]));
                b1 = pack_h2(__float2half_rn(P[(kb + 2) * DD + pcol]),
                             __float2half_rn(P[(kb + 3) * DD + pcol]));
            } else {
                int c = 8 * nt + tq - DD;      // class index
                if (c < CC) {
                    const float* mp = sMuP + c * DD;
                    b0 = pack_h2(__float2half_rn(mp[kb]),     __float2half_rn(mp[kb + 1]));
                    b1 = pack_h2(__float2half_rn(mp[kb + 2]), __float2half_rn(mp[kb + 3]));
                } else { b0 = 0u; b1 = 0u; }
            }
            Bf[kk][nt][0] = b0;
            Bf[kk][nt][1] = b1;
        }
    }

    const float alpha0 = __ldg(alpha_p);
    // cross acc cols: nt8 -> classes 2q, 2q+1; nt9 -> 8+2q, 9+2q (valid for q==0)
    const float nqA = sNegQ[2 * q];
    const float nqB = sNegQ[2 * q + 1];
    const float nq8 = sNegQ[8];
    const float nq9 = sNegQ[9];

    const int gw = blockIdx.x * 4 + w;
    const int stride = gridDim.x * 4;
    const float4* Fb = reinterpret_cast<const float4*>(F);
    const int sc = l & 15;

    uint32_t Ah[2][4][4];

    // issue one 32-row tile's 16 cp.asyncs into stage s
    auto issue = [&](int t, int s) {
        if (t < nTiles32) {
            const float4* src = Fb + (size_t)t * 512;
            uint32_t dst = uStage + (uint32_t)s * 8192u;
            #pragma unroll
            for (int j = 0; j < 16; j++) {
                int row = 2 * j + (l >> 4);
                cp_async16(dst + st_off(row, sc), src + (j * 32 + l));
            }
        }
        cp_commit();
    };
    // convert stage s -> hi frags for both 16-row halves
    auto convert = [&](int s) {
        uint32_t base = uStage + (uint32_t)s * 8192u;
        #pragma unroll
        for (int h = 0; h < 2; h++) {
            #pragma unroll
            for (int kk = 0; kk < 4; kk++) {
                int c0 = q + 4 * kk;
                float4 v0 = lds128(base + st_off(16 * h + tq, c0));
                float4 v1 = lds128(base + st_off(16 * h + tq + 8, c0));
                Ah[h][kk][0] = cvt_h2(v0.x, v0.y);
                Ah[h][kk][1] = cvt_h2(v1.x, v1.y);
                Ah[h][kk][2] = cvt_h2(v0.z, v0.w);
                Ah[h][kk][3] = cvt_h2(v1.z, v1.w);
            }
        }
    };

    // ---- prologue ----
    issue(gw, 0);
    asm volatile("cp.async.wait_group 0;" ::: "memory");
    __syncwarp();
    if (gw < nTiles32) convert(0);
    issue(gw + stride, 1);

    int si = 0;
    for (int tile = gw; tile < nTiles32; tile += stride) {
        int s2 = si + 2; if (s2 >= 3) s2 -= 3;
        issue(tile + 2 * stride, s2);

        const uint32_t fbase = uStage + (uint32_t)si * 8192u;

        // ---- cross MMAs (16): accC[h][ntc], write-init on kk=0 ----
        float accC[2][2][4];
        #pragma unroll
        for (int h = 0; h < 2; h++) {
            mma16816_z(accC[h][0], Ah[h][0], Bf[0][8]);
            mma16816_z(accC[h][1], Ah[h][0], Bf[0][9]);
        }
        #pragma unroll
        for (int kk = 1; kk < 4; kk++) {
            #pragma unroll
            for (int h = 0; h < 2; h++) {
                mma16816(accC[h][0], Ah[h][kk], Bf[kk][8]);
                mma16816(accC[h][1], Ah[h][kk], Bf[kk][9]);
            }
        }

        // ---- P block: 2 groups of 4 nt, qf folded per group, w = 2f - fh ----
        float qf[2][2] = {{0.f, 0.f}, {0.f, 0.f}};
        #pragma unroll
        for (int g = 0; g < 2; g++) {
            float accP[2][4][4];
            #pragma unroll
            for (int j = 0; j < 4; j++) {
                mma16816_z(accP[0][j], Ah[0][0], Bf[0][4 * g + j]);
                mma16816_z(accP[1][j], Ah[1][0], Bf[0][4 * g + j]);
            }
            #pragma unroll
            for (int kk = 1; kk < 4; kk++)
                #pragma unroll
                for (int j = 0; j < 4; j++) {
                    mma16816(accP[0][j], Ah[0][kk], Bf[kk][4 * g + j]);
                    mma16816(accP[1][j], Ah[1][kk], Bf[kk][4 * g + j]);
                }
            // fold: nt = 2*kk2 (j0) and 2*kk2+1 (j0+1), kk2 in {2g, 2g+1}
            #pragma unroll
            for (int kx = 0; kx < 2; kx++) {
                int kk2 = 2 * g + kx;
                int j0 = 2 * kx;            // = 2*kk2 - 4*g
                int c0 = q + 4 * kk2;
                #pragma unroll
                for (int h = 0; h < 2; h++) {
                    float4 v0 = lds128(fbase + st_off(16 * h + tq, c0));
                    float4 v1 = lds128(fbase + st_off(16 * h + tq + 8, c0));
                    float2 h0a = h2f(Ah[h][kk2][0]), h1a = h2f(Ah[h][kk2][1]);
                    float2 h0b = h2f(Ah[h][kk2][2]), h1b = h2f(Ah[h][kk2][3]);
                    // nt even (j0): elements x,y
                    qf[h][0] = fmaf(fmaf(2.f, v0.x, -h0a.x), accP[h][j0][0], qf[h][0]);
                    qf[h][0] = fmaf(fmaf(2.f, v0.y, -h0a.y), accP[h][j0][1], qf[h][0]);
                    qf[h][1] = fmaf(fmaf(2.f, v1.x, -h1a.x), accP[h][j0][2], qf[h][1]);
                    qf[h][1] = fmaf(fmaf(2.f, v1.y, -h1a.y), accP[h][j0][3], qf[h][1]);
                    // nt odd (j0+1): elements z,w
                    qf[h][0] = fmaf(fmaf(2.f, v0.z, -h0b.x), accP[h][j0 + 1][0], qf[h][0]);
                    qf[h][0] = fmaf(fmaf(2.f, v0.w, -h0b.y), accP[h][j0 + 1][1], qf[h][0]);
                    qf[h][1] = fmaf(fmaf(2.f, v1.z, -h1b.x), accP[h][j0 + 1][2], qf[h][1]);
                    qf[h][1] = fmaf(fmaf(2.f, v1.w, -h1b.y), accP[h][j0 + 1][3], qf[h][1]);
                }
            }
        }

        // ---- Ah dead: convert next tile now; overlaps epilogue tail ----
        cp_wait1();
        __syncwarp();
        int s1i = si + 1; if (s1i >= 3) s1i -= 3;
        if (tile + stride < nTiles32) convert(s1i);

        // ---- epilogue per half ----
        #pragma unroll
        for (int h = 0; h < 2; h++) {
            float s0 = fmaxf(accC[h][0][0] + nqA, accC[h][0][1] + nqB);
            float s1 = fmaxf(accC[h][0][2] + nqA, accC[h][0][3] + nqB);
            if (q == 0) {
                s0 = fmaxf(s0, fmaxf(accC[h][1][0] + nq8, accC[h][1][1] + nq9));
                s1 = fmaxf(s1, fmaxf(accC[h][1][2] + nq8, accC[h][1][3] + nq9));
            }
            float qf0 = qf[h][0], qf1 = qf[h][1];
            #pragma unroll
            for (int o = 1; o <= 2; o <<= 1) {
                qf0 += __shfl_xor_sync(0xffffffffu, qf0, o);
                qf1 += __shfl_xor_sync(0xffffffffu, qf1, o);
                s0 = fmaxf(s0, __shfl_xor_sync(0xffffffffu, s0, o));
                s1 = fmaxf(s1, __shfl_xor_sync(0xffffffffu, s1, o));
            }
            if (q == 0) {
                float* o = out + (size_t)tile * 32 + 16 * h;
                o[tq]     = alpha0 * (s0 - 0.5f * qf0);
                o[tq + 8] = alpha0 * (s1 - 0.5f * qf1);
            }
        }
        si = s1i;
    }
}

extern "C" void kernel_launch(void* const* d_in, const int* in_sizes, int n_in,
                              void* d_out, int out_size) {
    const float* features = (const float*)d_in[0];
    const float* mu       = (const float*)d_in[1];
    const float* P        = (const float*)d_in[2];
    const float* alpha    = (const float*)d_in[3];
    float* out = (float*)d_out;

    int n = in_sizes[0] / DD;
    int nTiles32 = n / 32;

    static bool attr_set = false;
    if (!attr_set) {
        cudaFuncSetAttribute(mahal_v16, cudaFuncAttributeMaxDynamicSharedMemorySize, 98304);
        attr_set = true;
    }

    mahal_v16<<<296, 128, 98304>>>(features, mu, P, alpha, out, nTiles32);
}

// round 17
// speedup vs baseline: 1.0414x; 1.0414x over previous
#include <cuda_runtime.h>
#include <cuda_fp16.h>
#include <cstdint>
#include <math_constants.h>

// Mahalanobis max-score: R15 structure (cp.async 3-stage warp-private pipeline,
// all-register HMMA, 32-row tiles = two independent 16-row streams, shared Bf,
// Al kept in registers for the qf fold) + write-init MMAs (no zero-init movs).
//   B cols 0..63: P fp16 (k-perm pi / n-perm sigma -> a-frags are raw float4s)
//   cols 64..73: hi fp16 of muP columns (classes), 74..79 zero pad
// qf = sum_k (fh + 2 fl)[k] * D[m,k]
// out[m] = alpha * (max_c (D_c - 0.5 qmu_c) - 0.5 * qf)

#define DD 64
#define CC 10
#define NT 10

static __device__ __forceinline__ uint32_t smem_u32(const void* p) {
    uint32_t a;
    asm("{ .reg .u64 t; cvta.to.shared.u64 t, %1; cvt.u32.u64 %0, t; }" : "=r"(a) : "l"(p));
    return a;
}
static __device__ __forceinline__ void cp_async16(uint32_t dst, const void* src) {
    asm volatile("cp.async.cg.shared.global [%0], [%1], 16;" :: "r"(dst), "l"(src) : "memory");
}
static __device__ __forceinline__ void cp_commit() {
    asm volatile("cp.async.commit_group;" ::: "memory");
}
static __device__ __forceinline__ void cp_wait1() {
    asm volatile("cp.async.wait_group 1;" ::: "memory");
}
static __device__ __forceinline__ float4 lds128(uint32_t addr) {
    float4 v;
    asm volatile("ld.shared.v4.f32 {%0,%1,%2,%3}, [%4];"
                 : "=f"(v.x), "=f"(v.y), "=f"(v.z), "=f"(v.w) : "r"(addr));
    return v;
}
// accumulate form: d += a*b
static __device__ __forceinline__ void mma16816(float* d, const uint32_t* a, const uint32_t* b) {
    asm volatile(
        "mma.sync.aligned.m16n8k16.row.col.f32.f16.f16.f32 "
        "{%0,%1,%2,%3}, {%4,%5,%6,%7}, {%8,%9}, {%0,%1,%2,%3};"
        : "+f"(d[0]), "+f"(d[1]), "+f"(d[2]), "+f"(d[3])
        : "r"(a[0]), "r"(a[1]), "r"(a[2]), "r"(a[3]), "r"(b[0]), "r"(b[1]));
}
// write-init form: d = a*b + 0 (no accumulator pre-zeroing needed)
static __device__ __forceinline__ void mma16816_z(float* d, const uint32_t* a, const uint32_t* b) {
    asm volatile(
        "mma.sync.aligned.m16n8k16.row.col.f32.f16.f16.f32 "
        "{%0,%1,%2,%3}, {%4,%5,%6,%7}, {%8,%9}, {%10,%10,%10,%10};"
        : "=f"(d[0]), "=f"(d[1]), "=f"(d[2]), "=f"(d[3])
        : "r"(a[0]), "r"(a[1]), "r"(a[2]), "r"(a[3]), "r"(b[0]), "r"(b[1]), "f"(0.f));
}
static __device__ __forceinline__ uint32_t pack_h2(__half a, __half b) {
    union { __half2 h; uint32_t u; } cv; cv.h = __halves2half2(a, b); return cv.u;
}
static __device__ __forceinline__ float2 h2f(uint32_t u) {
    union { uint32_t u; __half2 h; } cv; cv.u = u; return __half22float2(cv.h);
}
static __device__ __forceinline__ void split2(float x, float y, uint32_t& h, uint32_t& l) {
    __half2 hh = __float22half2_rn(make_float2(x, y));
    float2 hf = __half22float2(hh);
    __half2 ll = __float22half2_rn(make_float2(x - hf.x, y - hf.y));
    union { __half2 h; uint32_t u; } a, b;
    a.h = hh; b.h = ll;
    h = a.u; l = b.u;
}
// stage layout: [32 rows][16 chunks of 16B]; chunk' = c ^ ((row & 3) << 2)
static __device__ __forceinline__ uint32_t st_off(int row, int c) {
    return (uint32_t)(row * 256 + ((c ^ ((row & 3) << 2)) << 4));
}

__global__ __launch_bounds__(128, 2)
void mahal_v17(const float* __restrict__ F, const float* __restrict__ mu,
               const float* __restrict__ P, const float* __restrict__ alpha_p,
               float* __restrict__ out, int nTiles32) {
    extern __shared__ __align__(16) uint8_t dynStage[];   // 4 warps x 3 stages x 8KB
    __shared__ float sMuP[CC * DD];
    __shared__ float sNegQ[16];

    const int tid = threadIdx.x;

    // ---- one-time prep: muP (fp32), -0.5*qmu ----
    for (int idx = tid; idx < CC * DD; idx += 128) {
        int c = idx >> 6, k = idx & 63;
        const float* mc = mu + c * DD;
        const float* pk = P + k * DD;        // P symmetric
        float s = 0.f;
        #pragma unroll 16
        for (int j = 0; j < DD; j++) s = fmaf(mc[j], pk[j], s);
        sMuP[idx] = s;
    }
    __syncthreads();
    if (tid < 16) {
        float v = 0.f;
        if (tid < CC) {
            float qq = 0.f;
            #pragma unroll 16
            for (int k = 0; k < DD; k++) qq = fmaf(sMuP[tid * DD + k], mu[tid * DD + k], qq);
            v = -0.5f * qq;
        }
        sNegQ[tid] = v;
    }
    __syncthreads();

    const int w  = tid >> 5;
    const int l  = tid & 31;
    const int q  = l & 3;
    const int tq = l >> 2;
    const uint32_t uStage = smem_u32(dynStage) + (uint32_t)w * 24576u;

    // ---- persistent B fragments, permuted layout (validated R10/R14/R15) ----
    uint32_t Bf[4][NT][2];
    #pragma unroll
    for (int kk = 0; kk < 4; kk++) {
        const int kb = 16 * kk + 4 * q;
        #pragma unroll
        for (int nt = 0; nt < NT; nt++) {
            uint32_t b0, b1;
            if (nt < 8) {
                int pcol = 16 * (nt >> 1) + 4 * (tq >> 1) + 2 * (nt & 1) + (tq & 1);
                b0 = pack_h2(__float2half_rn(P[(kb    ) * DD + pcol]),
                             __float2half_rn(P[(kb + 1) * DD + pcol]));
                b1 = pack_h2(__float2half_rn(P[(kb + 2) * DD + pcol]),
                             __float2half_rn(P[(kb + 3) * DD + pcol]));
            } else {
                int c = 8 * nt + tq - DD;      // class index
                if (c < CC) {
                    const float* mp = sMuP + c * DD;
                    b0 = pack_h2(__float2half_rn(mp[kb]),     __float2half_rn(mp[kb + 1]));
                    b1 = pack_h2(__float2half_rn(mp[kb + 2]), __float2half_rn(mp[kb + 3]));
                } else { b0 = 0u; b1 = 0u; }
            }
            Bf[kk][nt][0] = b0;
            Bf[kk][nt][1] = b1;
        }
    }

    const float alpha0 = __ldg(alpha_p);
    // cross acc cols: nt8 -> classes 2q, 2q+1; nt9 -> 8+2q, 9+2q (valid for q==0)
    const float nqA = sNegQ[2 * q];
    const float nqB = sNegQ[2 * q + 1];
    const float nq8 = sNegQ[8];
    const float nq9 = sNegQ[9];

    const int gw = blockIdx.x * 4 + w;
    const int stride = gridDim.x * 4;
    const float4* Fb = reinterpret_cast<const float4*>(F);
    const int sc = l & 15;

    uint32_t Ah[2][4][4], Al[2][4][4];

    // issue one 32-row tile's 16 cp.asyncs into stage s
    auto issue = [&](int t, int s) {
        if (t < nTiles32) {
            const float4* src = Fb + (size_t)t * 512;
            uint32_t dst = uStage + (uint32_t)s * 8192u;
            #pragma unroll
            for (int j = 0; j < 16; j++) {
                int row = 2 * j + (l >> 4);
                cp_async16(dst + st_off(row, sc), src + (j * 32 + l));
            }
        }
        cp_commit();
    };
    // convert stage s -> hi/lo frags for both 16-row halves
    auto convert = [&](int s) {
        uint32_t base = uStage + (uint32_t)s * 8192u;
        #pragma unroll
        for (int h = 0; h < 2; h++) {
            #pragma unroll
            for (int kk = 0; kk < 4; kk++) {
                int c0 = q + 4 * kk;
                float4 v0 = lds128(base + st_off(16 * h + tq, c0));
                float4 v1 = lds128(base + st_off(16 * h + tq + 8, c0));
                split2(v0.x, v0.y, Ah[h][kk][0], Al[h][kk][0]);
                split2(v1.x, v1.y, Ah[h][kk][1], Al[h][kk][1]);
                split2(v0.z, v0.w, Ah[h][kk][2], Al[h][kk][2]);
                split2(v1.z, v1.w, Ah[h][kk][3], Al[h][kk][3]);
            }
        }
    };

    // ---- prologue ----
    issue(gw, 0);
    asm volatile("cp.async.wait_group 0;" ::: "memory");
    __syncwarp();
    if (gw < nTiles32) convert(0);
    issue(gw + stride, 1);

    int si = 0;
    for (int tile = gw; tile < nTiles32; tile += stride) {
        int s2 = si + 2; if (s2 >= 3) s2 -= 3;
        issue(tile + 2 * stride, s2);

        // ---- cross MMAs (16): accC[h][ntc], write-init on kk=0 ----
        float accC[2][2][4];
        #pragma unroll
        for (int h = 0; h < 2; h++) {
            mma16816_z(accC[h][0], Ah[h][0], Bf[0][8]);
            mma16816_z(accC[h][1], Ah[h][0], Bf[0][9]);
        }
        #pragma unroll
        for (int kk = 1; kk < 4; kk++) {
            #pragma unroll
            for (int h = 0; h < 2; h++) {
                mma16816(accC[h][0], Ah[h][kk], Bf[kk][8]);
                mma16816(accC[h][1], Ah[h][kk], Bf[kk][9]);
            }
        }

        // ---- P block: 2 groups of 4 nt, both halves, write-init kk=0,
        //      qf folded per group from Ah/Al registers (R15 fold) ----
        float qf[2][2] = {{0.f, 0.f}, {0.f, 0.f}};
        #pragma unroll
        for (int g = 0; g < 2; g++) {
            float accP[2][4][4];
            #pragma unroll
            for (int j = 0; j < 4; j++) {
                mma16816_z(accP[0][j], Ah[0][0], Bf[0][4 * g + j]);
                mma16816_z(accP[1][j], Ah[1][0], Bf[0][4 * g + j]);
            }
            #pragma unroll
            for (int kk = 1; kk < 4; kk++)
                #pragma unroll
                for (int j = 0; j < 4; j++) {
                    mma16816(accP[0][j], Ah[0][kk], Bf[kk][4 * g + j]);
                    mma16816(accP[1][j], Ah[1][kk], Bf[kk][4 * g + j]);
                }
            #pragma unroll
            for (int j = 0; j < 4; j++) {
                int nt = 4 * g + j;
                int kk = nt >> 1;
                int i0 = (nt & 1) ? 2 : 0;
                #pragma unroll
                for (int h = 0; h < 2; h++) {
                    float2 h0 = h2f(Ah[h][kk][i0]),     l0 = h2f(Al[h][kk][i0]);
                    float2 h1 = h2f(Ah[h][kk][i0 + 1]), l1 = h2f(Al[h][kk][i0 + 1]);
                    qf[h][0] = fmaf(fmaf(2.f, l0.x, h0.x), accP[h][j][0], qf[h][0]);
                    qf[h][0] = fmaf(fmaf(2.f, l0.y, h0.y), accP[h][j][1], qf[h][0]);
                    qf[h][1] = fmaf(fmaf(2.f, l1.x, h1.x), accP[h][j][2], qf[h][1]);
                    qf[h][1] = fmaf(fmaf(2.f, l1.y, h1.y), accP[h][j][3], qf[h][1]);
                }
            }
        }

        // ---- Ah/Al dead: convert next tile now; overlaps epilogue tail ----
        cp_wait1();
        __syncwarp();
        int s1i = si + 1; if (s1i >= 3) s1i -= 3;
        if (tile + stride < nTiles32) convert(s1i);

        // ---- epilogue per half ----
        #pragma unroll
        for (int h = 0; h < 2; h++) {
            float s0 = fmaxf(accC[h][0][0] + nqA, accC[h][0][1] + nqB);
            float s1 = fmaxf(accC[h][0][2] + nqA, accC[h][0][3] + nqB);
            if (q == 0) {
                s0 = fmaxf(s0, fmaxf(accC[h][1][0] + nq8, accC[h][1][1] + nq9));
                s1 = fmaxf(s1, fmaxf(accC[h][1][2] + nq8, accC[h][1][3] + nq9));
            }
            float qf0 = qf[h][0], qf1 = qf[h][1];
            #pragma unroll
            for (int o = 1; o <= 2; o <<= 1) {
                qf0 += __shfl_xor_sync(0xffffffffu, qf0, o);
                qf1 += __shfl_xor_sync(0xffffffffu, qf1, o);
                s0 = fmaxf(s0, __shfl_xor_sync(0xffffffffu, s0, o));
                s1 = fmaxf(s1, __shfl_xor_sync(0xffffffffu, s1, o));
            }
            if (q == 0) {
                float* o = out + (size_t)tile * 32 + 16 * h;
                o[tq]     = alpha0 * (s0 - 0.5f * qf0);
                o[tq + 8] = alpha0 * (s1 - 0.5f * qf1);
            }
        }
        si = s1i;
    }
}

extern "C" void kernel_launch(void* const* d_in, const int* in_sizes, int n_in,
                              void* d_out, int out_size) {
    const float* features = (const float*)d_in[0];
    const float* mu       = (const float*)d_in[1];
    const float* P        = (const float*)d_in[2];
    const float* alpha    = (const float*)d_in[3];
    float* out = (float*)d_out;

    int n = in_sizes[0] / DD;
    int nTiles32 = n / 32;

    static bool attr_set = false;
    if (!attr_set) {
        cudaFuncSetAttribute(mahal_v17, cudaFuncAttributeMaxDynamicSharedMemorySize, 98304);
        attr_set = true;
    }

    mahal_v17<<<296, 128, 98304>>>(features, mu, P, alpha, out, nTiles32);
}